// round 2
// baseline (speedup 1.0000x reference)
#include <cuda_runtime.h>

// CASSI forward, two-phase tiled version.
//
// Phase A (per block): stage a TN x 64 tile of x (row m, cols [n0, n0+TN))
//   into shared memory via float4 streaming loads, folding in ca[m,n].
// Phase B: per-output rotation-indexed diagonal reduction from smem.
//   y[m, n0+cr] = sum_l tile[cr-l][l],  cr in [0, TN+62]
//   Interior outputs (cr in [63, TN-1]) have all contributors inside the
//   tile -> plain store. Boundary outputs are shared with the adjacent
//   tile -> atomicAdd into zero-initialized y.
//
// x  : (1, 1024, 1024, 64) f32   ca : (1, 1024, 1024, 1) f32
// y  : (1, 1024, 1087, 1) f32

#define MM     1024
#define NN     1024
#define LL     64
#define OUTC   (NN + LL - 1)      // 1087
#define TN     256                // n-rows per tile
#define NT     256                // threads per block
#define NTILES (NN / TN)          // 4
#define SMEM_BYTES ((TN * LL + TN) * sizeof(float))  // 66560 B

__global__ void cassi_zero_kernel(float4* __restrict__ y4, int n4)
{
    int i = blockIdx.x * blockDim.x + threadIdx.x;
    if (i < n4) y4[i] = make_float4(0.f, 0.f, 0.f, 0.f);
}

__global__ __launch_bounds__(NT)
void cassi_tile_kernel(const float* __restrict__ x,
                       const float* __restrict__ ca,
                       float* __restrict__ y)
{
    extern __shared__ float smem[];
    float* s_tile = smem;            // TN * LL floats
    float* s_ca   = smem + TN * LL;  // TN floats

    const int m   = blockIdx.y;
    const int n0  = blockIdx.x * TN;
    const int tid = threadIdx.x;

    // ---- Phase A: stage tile, fold ca ----
    s_ca[tid] = ca[m * NN + n0 + tid];
    __syncthreads();

    const float4* xv = (const float4*)(x + ((size_t)m * NN + n0) * LL);
    float4*       tv = (float4*)s_tile;

    #pragma unroll
    for (int k = 0; k < (TN * LL / 4) / NT; ++k) {   // 16 iterations
        const int idx = tid + k * NT;                // float4 index in tile
        float4 v = xv[idx];
        const float s = s_ca[idx >> 4];              // 16 float4 per n-row
        v.x *= s; v.y *= s; v.z *= s; v.w *= s;
        tv[idx] = v;
    }
    __syncthreads();

    // ---- Phase B: diagonal reduction ----
    float* yrow = y + (size_t)m * OUTC;

    // thread handles cr = tid, and cr = TN + tid for tid < LL-1
    #pragma unroll 1
    for (int cr = tid; cr < TN + LL - 1; cr += NT) {
        float acc = 0.f;
        #pragma unroll
        for (int j = 0; j < LL; ++j) {
            const int l = (cr + j) & (LL - 1);       // rotation: bank-conflict free
            const int n = cr - l;
            if ((unsigned)n < TN)
                acc += s_tile[n * LL + l];
        }
        const int c = n0 + cr;
        if (cr >= LL - 1 && cr < TN)
            yrow[c] = acc;                           // interior: sole contributor
        else
            atomicAdd(&yrow[c], acc);                // boundary: shared with neighbor
    }
}

extern "C" void kernel_launch(void* const* d_in, const int* in_sizes, int n_in,
                              void* d_out, int out_size)
{
    const float* x  = (const float*)d_in[0];
    const float* ca = (const float*)d_in[1];
    float* y        = (float*)d_out;

    cudaFuncSetAttribute(cassi_tile_kernel,
                         cudaFuncAttributeMaxDynamicSharedMemorySize,
                         (int)SMEM_BYTES);

    // zero-init y (d_out is poisoned to 0xAA by the harness)
    const int n4 = (MM * OUTC) / 4;                  // 1087*1024/4, divisible
    cassi_zero_kernel<<<(n4 + 255) / 256, 256>>>((float4*)y, n4);

    cassi_tile_kernel<<<dim3(NTILES, MM), NT, SMEM_BYTES>>>(x, ca, y);
}